// round 1
// baseline (speedup 1.0000x reference)
#include <cuda_runtime.h>
#include <cuda_bf16.h>
#include <math_constants.h>

#define B_SZ 4
#define T_SEQ 4096
#define C_DIM 768
#define HD 64

// Scratch for q,k,v projections: [B, T, H] each = 4*4096*64 floats = 4MB each.
__device__ float g_q[B_SZ * T_SEQ * HD];
__device__ float g_k[B_SZ * T_SEQ * HD];
__device__ float g_v[B_SZ * T_SEQ * HD];

// ---------------------------------------------------------------------------
// Kernel 1: fused QKV projection.
// q/k/v[b,t,h] = sum_c x[b,t,c] * W{q,k,v}[c,h]
// GEMM: M = B*T = 16384, K = 768, N = 64, three outputs sharing the x reads.
// Block: 64 rows of x, 256 threads (16x16), each thread 4 rows x 4 cols x 3 mats.
// ---------------------------------------------------------------------------
__global__ __launch_bounds__(256) void proj_kernel(
    const float* __restrict__ x,
    const float* __restrict__ Wq,
    const float* __restrict__ Wk,
    const float* __restrict__ Wv)
{
    __shared__ float sX[64][33];      // 64 rows x 32 k (+1 pad)
    __shared__ float sW[3][32][64];   // 3 matrices, 32 k x 64 h

    const int tx = threadIdx.x;
    const int ty = threadIdx.y;
    const int tid = ty * 16 + tx;
    const int row0 = blockIdx.x * 64;   // global row base (flattened b*T+t)
    const int r0 = ty * 4;
    const int c0 = tx * 4;

    float acc[3][4][4];
    #pragma unroll
    for (int m = 0; m < 3; m++)
        #pragma unroll
        for (int r = 0; r < 4; r++)
            #pragma unroll
            for (int c = 0; c < 4; c++)
                acc[m][r][c] = 0.f;

    for (int k0 = 0; k0 < C_DIM; k0 += 32) {
        // load x tile: 64x32 = 2048 floats, 8 per thread, coalesced
        #pragma unroll
        for (int t = 0; t < 8; t++) {
            int i = tid + t * 256;
            int rr = i >> 5;
            int cc = i & 31;
            sX[rr][cc] = x[(size_t)(row0 + rr) * C_DIM + k0 + cc];
        }
        // load W tiles: 32x64 each
        #pragma unroll
        for (int t = 0; t < 8; t++) {
            int i = tid + t * 256;
            int kk = i >> 6;
            int cc = i & 63;
            sW[0][kk][cc] = Wq[(size_t)(k0 + kk) * HD + cc];
            sW[1][kk][cc] = Wk[(size_t)(k0 + kk) * HD + cc];
            sW[2][kk][cc] = Wv[(size_t)(k0 + kk) * HD + cc];
        }
        __syncthreads();

        #pragma unroll
        for (int kk = 0; kk < 32; kk++) {
            float xf[4];
            #pragma unroll
            for (int r = 0; r < 4; r++) xf[r] = sX[r0 + r][kk];
            float4 wq = *(const float4*)&sW[0][kk][c0];
            float4 wk = *(const float4*)&sW[1][kk][c0];
            float4 wv = *(const float4*)&sW[2][kk][c0];
            #pragma unroll
            for (int r = 0; r < 4; r++) {
                acc[0][r][0] += xf[r] * wq.x;
                acc[0][r][1] += xf[r] * wq.y;
                acc[0][r][2] += xf[r] * wq.z;
                acc[0][r][3] += xf[r] * wq.w;
                acc[1][r][0] += xf[r] * wk.x;
                acc[1][r][1] += xf[r] * wk.y;
                acc[1][r][2] += xf[r] * wk.z;
                acc[1][r][3] += xf[r] * wk.w;
                acc[2][r][0] += xf[r] * wv.x;
                acc[2][r][1] += xf[r] * wv.y;
                acc[2][r][2] += xf[r] * wv.z;
                acc[2][r][3] += xf[r] * wv.w;
            }
        }
        __syncthreads();
    }

    // write out
    #pragma unroll
    for (int r = 0; r < 4; r++) {
        size_t base = (size_t)(row0 + r0 + r) * HD + c0;
        *(float4*)&g_q[base] = make_float4(acc[0][r][0], acc[0][r][1], acc[0][r][2], acc[0][r][3]);
        *(float4*)&g_k[base] = make_float4(acc[1][r][0], acc[1][r][1], acc[1][r][2], acc[1][r][3]);
        *(float4*)&g_v[base] = make_float4(acc[2][r][0], acc[2][r][1], acc[2][r][2], acc[2][r][3]);
    }
}

// ---------------------------------------------------------------------------
// Kernel 2: causal flash attention. One block per (batch, 64-query-row tile).
// Online softmax, BN=64 KV tiles, fp32 FFMA, float4-vectorized smem.
// smem: sQ[64][64], sK[64][68], sV[64][64], sP[64][68] (floats), dynamic.
// ---------------------------------------------------------------------------
__global__ __launch_bounds__(256) void flash_kernel(float* __restrict__ out)
{
    extern __shared__ float smem[];
    float* sQ = smem;                 // 64*64   = 4096
    float* sK = sQ + 64 * 64;         // 64*68   = 4352 (pad keeps 16B align)
    float* sV = sK + 64 * 68;         // 64*64   = 4096
    float* sP = sV + 64 * 64;         // 64*68   = 4352

    float4* sQ4 = (float4*)sQ;
    float4* sK4 = (float4*)sK;
    float4* sV4 = (float4*)sV;
    float4* sP4 = (float4*)sP;

    const int tx = threadIdx.x;
    const int ty = threadIdx.y;
    const int tid = ty * 16 + tx;
    const int iq = blockIdx.x;        // query tile index
    const int b = blockIdx.y;
    const int r0 = ty * 4;
    const int c0 = tx * 4;

    const float4* gq4 = (const float4*)(g_q + ((size_t)b * T_SEQ + iq * 64) * HD);
    const float4* gk4 = (const float4*)(g_k + (size_t)b * T_SEQ * HD);
    const float4* gv4 = (const float4*)(g_v + (size_t)b * T_SEQ * HD);

    // load Q tile: 64 rows * 16 float4
    #pragma unroll
    for (int t = 0; t < 4; t++) {
        int i = tid + t * 256;
        sQ4[i] = gq4[i];
    }

    float m_r[4], l_r[4];
    float acc[4][4];
    #pragma unroll
    for (int r = 0; r < 4; r++) {
        m_r[r] = -CUDART_INF_F;
        l_r[r] = 0.f;
        #pragma unroll
        for (int c = 0; c < 4; c++) acc[r][c] = 0.f;
    }

    for (int j = 0; j <= iq; j++) {
        // load K,V tiles
        #pragma unroll
        for (int t = 0; t < 4; t++) {
            int i = tid + t * 256;
            int rr = i >> 4;
            int c4 = i & 15;
            float4 kv = gk4[(size_t)(j * 64 + rr) * 16 + c4];
            float4 vv = gv4[(size_t)(j * 64 + rr) * 16 + c4];
            sK4[rr * 17 + c4] = kv;
            sV4[i] = vv;
        }
        __syncthreads();

        // S = Q K^T (scaled)
        float s[4][4];
        #pragma unroll
        for (int r = 0; r < 4; r++)
            #pragma unroll
            for (int c = 0; c < 4; c++) s[r][c] = 0.f;

        #pragma unroll
        for (int d4 = 0; d4 < 16; d4++) {
            float4 qf[4], kf[4];
            #pragma unroll
            for (int r = 0; r < 4; r++) qf[r] = sQ4[(r0 + r) * 16 + d4];
            #pragma unroll
            for (int c = 0; c < 4; c++) kf[c] = sK4[(c0 + c) * 17 + d4];
            #pragma unroll
            for (int r = 0; r < 4; r++)
                #pragma unroll
                for (int c = 0; c < 4; c++) {
                    s[r][c] += qf[r].x * kf[c].x;
                    s[r][c] += qf[r].y * kf[c].y;
                    s[r][c] += qf[r].z * kf[c].z;
                    s[r][c] += qf[r].w * kf[c].w;
                }
        }

        const bool diag = (j == iq);
        // online softmax per row group; rows owned by this thread: r0..r0+3
        #pragma unroll
        for (int r = 0; r < 4; r++) {
            float sv[4];
            #pragma unroll
            for (int c = 0; c < 4; c++) {
                float v = s[r][c] * 0.125f;   // 1/sqrt(64)
                if (diag && (c0 + c > r0 + r)) v = -CUDART_INF_F;
                sv[c] = v;
            }
            float mx = fmaxf(fmaxf(sv[0], sv[1]), fmaxf(sv[2], sv[3]));
            #pragma unroll
            for (int off = 8; off >= 1; off >>= 1)
                mx = fmaxf(mx, __shfl_xor_sync(0xffffffffu, mx, off));
            float mnew = fmaxf(m_r[r], mx);
            float alpha = __expf(m_r[r] - mnew);
            float p[4], rs = 0.f;
            #pragma unroll
            for (int c = 0; c < 4; c++) {
                p[c] = __expf(sv[c] - mnew);
                rs += p[c];
            }
            #pragma unroll
            for (int off = 8; off >= 1; off >>= 1)
                rs += __shfl_xor_sync(0xffffffffu, rs, off);
            l_r[r] = l_r[r] * alpha + rs;
            m_r[r] = mnew;
            #pragma unroll
            for (int c = 0; c < 4; c++) acc[r][c] *= alpha;
            sP4[(r0 + r) * 17 + tx] = make_float4(p[0], p[1], p[2], p[3]);
        }
        __syncthreads();

        // acc += P @ V
        #pragma unroll
        for (int s4 = 0; s4 < 16; s4++) {
            float pf[4][4];
            #pragma unroll
            for (int r = 0; r < 4; r++) {
                float4 t4 = sP4[(r0 + r) * 17 + s4];
                pf[r][0] = t4.x; pf[r][1] = t4.y; pf[r][2] = t4.z; pf[r][3] = t4.w;
            }
            float vf[4][4];
            #pragma unroll
            for (int cs = 0; cs < 4; cs++) {
                float4 t4 = sV4[(s4 * 4 + cs) * 16 + tx];
                vf[cs][0] = t4.x; vf[cs][1] = t4.y; vf[cs][2] = t4.z; vf[cs][3] = t4.w;
            }
            #pragma unroll
            for (int r = 0; r < 4; r++)
                #pragma unroll
                for (int h = 0; h < 4; h++) {
                    acc[r][h] += pf[r][0] * vf[0][h];
                    acc[r][h] += pf[r][1] * vf[1][h];
                    acc[r][h] += pf[r][2] * vf[2][h];
                    acc[r][h] += pf[r][3] * vf[3][h];
                }
        }
        __syncthreads();
    }

    // epilogue: normalize & store
    float4* out4 = (float4*)out;
    #pragma unroll
    for (int r = 0; r < 4; r++) {
        float inv = 1.f / l_r[r];
        size_t row = (size_t)b * T_SEQ + iq * 64 + r0 + r;
        out4[row * 16 + tx] = make_float4(acc[r][0] * inv, acc[r][1] * inv,
                                          acc[r][2] * inv, acc[r][3] * inv);
    }
}

extern "C" void kernel_launch(void* const* d_in, const int* in_sizes, int n_in,
                              void* d_out, int out_size)
{
    const float* x  = (const float*)d_in[0];
    const float* Wq = (const float*)d_in[1];
    const float* Wk = (const float*)d_in[2];
    const float* Wv = (const float*)d_in[3];
    float* out = (float*)d_out;

    dim3 tb(16, 16);
    proj_kernel<<<(B_SZ * T_SEQ) / 64, tb>>>(x, Wq, Wk, Wv);

    size_t smem_bytes = (size_t)(64 * 64 + 64 * 68 + 64 * 64 + 64 * 68) * sizeof(float);
    cudaFuncSetAttribute(flash_kernel, cudaFuncAttributeMaxDynamicSharedMemorySize,
                         (int)smem_bytes);
    flash_kernel<<<dim3(T_SEQ / 64, B_SZ), tb, smem_bytes>>>(out);
}

// round 3
// speedup vs baseline: 4.0625x; 4.0625x over previous
#include <cuda_runtime.h>
#include <cuda_fp16.h>
#include <math_constants.h>
#include <cstdint>

#define B_SZ 4
#define T_SEQ 4096
#define C_DIM 768
#define HD 64

// fp16 scratch: q,k as [B,T,H]; vt transposed as [B,H,T]
__device__ __half g_q[B_SZ * T_SEQ * HD];
__device__ __half g_k[B_SZ * T_SEQ * HD];
__device__ __half g_vt[B_SZ * HD * T_SEQ];

// ---------------------------------------------------------------------------
// Kernel 1: fused QKV projection (fp32 FFMA), fp16 outputs; v written transposed.
// ---------------------------------------------------------------------------
__global__ __launch_bounds__(256) void proj_kernel(
    const float* __restrict__ x,
    const float* __restrict__ Wq,
    const float* __restrict__ Wk,
    const float* __restrict__ Wv)
{
    __shared__ float sX[64][33];
    __shared__ float sW[3][32][64];
    __shared__ __half sVst[64 * 72];   // staged v^T tile: [h][t]

    const int tx = threadIdx.x;
    const int ty = threadIdx.y;
    const int tid = ty * 16 + tx;
    const int row0 = blockIdx.x * 64;
    const int r0 = ty * 4;
    const int c0 = tx * 4;

    float acc[3][4][4];
    #pragma unroll
    for (int m = 0; m < 3; m++)
        #pragma unroll
        for (int r = 0; r < 4; r++)
            #pragma unroll
            for (int c = 0; c < 4; c++)
                acc[m][r][c] = 0.f;

    for (int k0 = 0; k0 < C_DIM; k0 += 32) {
        #pragma unroll
        for (int t = 0; t < 8; t++) {
            int i = tid + t * 256;
            int rr = i >> 5;
            int cc = i & 31;
            sX[rr][cc] = x[(size_t)(row0 + rr) * C_DIM + k0 + cc];
        }
        #pragma unroll
        for (int t = 0; t < 8; t++) {
            int i = tid + t * 256;
            int kk = i >> 6;
            int cc = i & 63;
            sW[0][kk][cc] = Wq[(size_t)(k0 + kk) * HD + cc];
            sW[1][kk][cc] = Wk[(size_t)(k0 + kk) * HD + cc];
            sW[2][kk][cc] = Wv[(size_t)(k0 + kk) * HD + cc];
        }
        __syncthreads();

        #pragma unroll
        for (int kk = 0; kk < 32; kk++) {
            float xf[4];
            #pragma unroll
            for (int r = 0; r < 4; r++) xf[r] = sX[r0 + r][kk];
            float4 wq = *(const float4*)&sW[0][kk][c0];
            float4 wk = *(const float4*)&sW[1][kk][c0];
            float4 wv = *(const float4*)&sW[2][kk][c0];
            #pragma unroll
            for (int r = 0; r < 4; r++) {
                acc[0][r][0] += xf[r] * wq.x;
                acc[0][r][1] += xf[r] * wq.y;
                acc[0][r][2] += xf[r] * wq.z;
                acc[0][r][3] += xf[r] * wq.w;
                acc[1][r][0] += xf[r] * wk.x;
                acc[1][r][1] += xf[r] * wk.y;
                acc[1][r][2] += xf[r] * wk.z;
                acc[1][r][3] += xf[r] * wk.w;
                acc[2][r][0] += xf[r] * wv.x;
                acc[2][r][1] += xf[r] * wv.y;
                acc[2][r][2] += xf[r] * wv.z;
                acc[2][r][3] += xf[r] * wv.w;
            }
        }
        __syncthreads();
    }

    // q, k: direct fp16 stores
    #pragma unroll
    for (int r = 0; r < 4; r++) {
        size_t base = (size_t)(row0 + r0 + r) * HD + c0;
        __half2 q01 = __floats2half2_rn(acc[0][r][0], acc[0][r][1]);
        __half2 q23 = __floats2half2_rn(acc[0][r][2], acc[0][r][3]);
        __half2 k01 = __floats2half2_rn(acc[1][r][0], acc[1][r][1]);
        __half2 k23 = __floats2half2_rn(acc[1][r][2], acc[1][r][3]);
        *(__half2*)&g_q[base] = q01;
        *(__half2*)&g_q[base + 2] = q23;
        *(__half2*)&g_k[base] = k01;
        *(__half2*)&g_k[base + 2] = k23;
    }

    // v: stage transposed in smem, then coalesced rows to g_vt[b][h][t]
    #pragma unroll
    for (int r = 0; r < 4; r++)
        #pragma unroll
        for (int c = 0; c < 4; c++)
            sVst[(c0 + c) * 72 + (r0 + r)] = __float2half(acc[2][r][c]);
    __syncthreads();

    const int bb = row0 / T_SEQ;
    const int t0 = row0 % T_SEQ;
    #pragma unroll
    for (int u = 0; u < 2; u++) {
        int i = tid + u * 256;
        int h = i >> 3;
        int ch = i & 7;
        uint4 val = *(const uint4*)&sVst[h * 72 + ch * 8];
        *(uint4*)(g_vt + (size_t)bb * HD * T_SEQ + (size_t)h * T_SEQ + t0 + ch * 8) = val;
    }
}

// ---------------------------------------------------------------------------
// Kernel 2: causal flash attention with HMMA m16n8k16 (fp16 in, fp32 acc).
// 128 threads = 4 warps; warp w owns 16 query rows x all 64 key cols.
// Heavy tiles launched first: iq = 63 - blockIdx.x.
// ---------------------------------------------------------------------------
__device__ __forceinline__ void mma16816(float c[4],
    uint32_t a0, uint32_t a1, uint32_t a2, uint32_t a3,
    uint32_t b0, uint32_t b1)
{
    asm volatile(
        "mma.sync.aligned.m16n8k16.row.col.f32.f16.f16.f32 "
        "{%0,%1,%2,%3}, {%4,%5,%6,%7}, {%8,%9}, {%0,%1,%2,%3};\n"
        : "+f"(c[0]), "+f"(c[1]), "+f"(c[2]), "+f"(c[3])
        : "r"(a0), "r"(a1), "r"(a2), "r"(a3), "r"(b0), "r"(b1));
}

#define FULLMASK 0xffffffffu
#define PSTR 72   // padded half-stride: conflict-free fragment access

__global__ __launch_bounds__(128) void flash2(float* __restrict__ out)
{
    __shared__ __half sQ[64 * PSTR];
    __shared__ __half sK[64 * PSTR];
    __shared__ __half sVt[64 * PSTR];
    __shared__ __half sP[64 * PSTR];

    const int tid = threadIdx.x;
    const int warp = tid >> 5;
    const int lane = tid & 31;
    const int g = lane >> 2;      // group id (row within mma tile)
    const int t = lane & 3;       // thread-in-group (col pairs)
    const int m0 = warp * 16;
    const int iq = (T_SEQ / 64 - 1) - blockIdx.x;  // heavy-first
    const int b = blockIdx.y;

    // load Q tile
    {
        const uint4* gq = (const uint4*)(g_q + ((size_t)b * T_SEQ + iq * 64) * HD);
        #pragma unroll
        for (int u = 0; u < 4; u++) {
            int i = tid + u * 128;
            int r = i >> 3, ch = i & 7;
            *(uint4*)&sQ[r * PSTR + ch * 8] = gq[r * 8 + ch];
        }
    }

    float oc[8][4];
    #pragma unroll
    for (int nt = 0; nt < 8; nt++)
        #pragma unroll
        for (int c = 0; c < 4; c++) oc[nt][c] = 0.f;
    float mr0 = -CUDART_INF_F, mr1 = -CUDART_INF_F;
    float l0 = 0.f, l1 = 0.f;

    const int rA = (m0 + g) * PSTR;       // row offsets (halves)
    const int rB = (m0 + g + 8) * PSTR;

    for (int j = 0; j <= iq; j++) {
        __syncthreads();
        {
            const uint4* gk = (const uint4*)(g_k + ((size_t)b * T_SEQ + j * 64) * HD);
            #pragma unroll
            for (int u = 0; u < 4; u++) {
                int i = tid + u * 128;
                int r = i >> 3, ch = i & 7;
                *(uint4*)&sK[r * PSTR + ch * 8] = gk[r * 8 + ch];
            }
            const __half* gvt = g_vt + (size_t)b * HD * T_SEQ + j * 64;
            #pragma unroll
            for (int u = 0; u < 4; u++) {
                int i = tid + u * 128;
                int h = i >> 3, ch = i & 7;
                *(uint4*)&sVt[h * PSTR + ch * 8] =
                    *(const uint4*)(gvt + (size_t)h * T_SEQ + ch * 8);
            }
        }
        __syncthreads();

        // S = Q K^T
        float sc[8][4];
        #pragma unroll
        for (int nt = 0; nt < 8; nt++)
            #pragma unroll
            for (int c = 0; c < 4; c++) sc[nt][c] = 0.f;

        #pragma unroll
        for (int ks = 0; ks < 4; ks++) {
            int ca = ks * 16 + t * 2;
            uint32_t A0 = *(const uint32_t*)&sQ[rA + ca];
            uint32_t A1 = *(const uint32_t*)&sQ[rB + ca];
            uint32_t A2 = *(const uint32_t*)&sQ[rA + ca + 8];
            uint32_t A3 = *(const uint32_t*)&sQ[rB + ca + 8];
            #pragma unroll
            for (int nt = 0; nt < 8; nt++) {
                uint32_t B0 = *(const uint32_t*)&sK[(nt * 8 + g) * PSTR + ca];
                uint32_t B1 = *(const uint32_t*)&sK[(nt * 8 + g) * PSTR + ca + 8];
                mma16816(sc[nt], A0, A1, A2, A3, B0, B1);
            }
        }

        // online softmax (rows m0+g and m0+g+8, cols within 4-lane group)
        const bool diag = (j == iq);
        float mx0 = -CUDART_INF_F, mx1 = -CUDART_INF_F;
        #pragma unroll
        for (int nt = 0; nt < 8; nt++) {
            int cl = nt * 8 + t * 2;
            float v0 = sc[nt][0] * 0.125f;
            float v1 = sc[nt][1] * 0.125f;
            float v2 = sc[nt][2] * 0.125f;
            float v3 = sc[nt][3] * 0.125f;
            if (diag) {
                int r0l = m0 + g, r1l = m0 + g + 8;
                if (cl     > r0l) v0 = -CUDART_INF_F;
                if (cl + 1 > r0l) v1 = -CUDART_INF_F;
                if (cl     > r1l) v2 = -CUDART_INF_F;
                if (cl + 1 > r1l) v3 = -CUDART_INF_F;
            }
            sc[nt][0] = v0; sc[nt][1] = v1; sc[nt][2] = v2; sc[nt][3] = v3;
            mx0 = fmaxf(mx0, fmaxf(v0, v1));
            mx1 = fmaxf(mx1, fmaxf(v2, v3));
        }
        mx0 = fmaxf(mx0, __shfl_xor_sync(FULLMASK, mx0, 1));
        mx0 = fmaxf(mx0, __shfl_xor_sync(FULLMASK, mx0, 2));
        mx1 = fmaxf(mx1, __shfl_xor_sync(FULLMASK, mx1, 1));
        mx1 = fmaxf(mx1, __shfl_xor_sync(FULLMASK, mx1, 2));

        float mn0 = fmaxf(mr0, mx0);
        float mn1 = fmaxf(mr1, mx1);
        float al0 = __expf(mr0 - mn0);
        float al1 = __expf(mr1 - mn1);
        float s0 = 0.f, s1 = 0.f;
        #pragma unroll
        for (int nt = 0; nt < 8; nt++) {
            float p0 = __expf(sc[nt][0] - mn0);
            float p1 = __expf(sc[nt][1] - mn0);
            float p2 = __expf(sc[nt][2] - mn1);
            float p3 = __expf(sc[nt][3] - mn1);
            s0 += p0 + p1;
            s1 += p2 + p3;
            int cl = nt * 8 + t * 2;
            *(__half2*)&sP[rA + cl] = __floats2half2_rn(p0, p1);
            *(__half2*)&sP[rB + cl] = __floats2half2_rn(p2, p3);
        }
        s0 += __shfl_xor_sync(FULLMASK, s0, 1);
        s0 += __shfl_xor_sync(FULLMASK, s0, 2);
        s1 += __shfl_xor_sync(FULLMASK, s1, 1);
        s1 += __shfl_xor_sync(FULLMASK, s1, 2);
        l0 = l0 * al0 + s0;
        l1 = l1 * al1 + s1;
        mr0 = mn0;
        mr1 = mn1;
        #pragma unroll
        for (int nt = 0; nt < 8; nt++) {
            oc[nt][0] *= al0;
            oc[nt][1] *= al0;
            oc[nt][2] *= al1;
            oc[nt][3] *= al1;
        }
        __syncwarp();

        // O += P V  (A-frags from own rows of sP; B from sVt[h][s])
        #pragma unroll
        for (int ks = 0; ks < 4; ks++) {
            int ca = ks * 16 + t * 2;
            uint32_t A0 = *(const uint32_t*)&sP[rA + ca];
            uint32_t A1 = *(const uint32_t*)&sP[rB + ca];
            uint32_t A2 = *(const uint32_t*)&sP[rA + ca + 8];
            uint32_t A3 = *(const uint32_t*)&sP[rB + ca + 8];
            #pragma unroll
            for (int nt = 0; nt < 8; nt++) {
                uint32_t B0 = *(const uint32_t*)&sVt[(nt * 8 + g) * PSTR + ca];
                uint32_t B1 = *(const uint32_t*)&sVt[(nt * 8 + g) * PSTR + ca + 8];
                mma16816(oc[nt], A0, A1, A2, A3, B0, B1);
            }
        }
    }

    // epilogue
    float inv0 = 1.f / l0;
    float inv1 = 1.f / l1;
    float* orow0 = out + ((size_t)b * T_SEQ + iq * 64 + m0 + g) * HD;
    float* orow1 = orow0 + (size_t)8 * HD;
    #pragma unroll
    for (int nt = 0; nt < 8; nt++) {
        int cl = nt * 8 + t * 2;
        float2 w0 = make_float2(oc[nt][0] * inv0, oc[nt][1] * inv0);
        float2 w1 = make_float2(oc[nt][2] * inv1, oc[nt][3] * inv1);
        *(float2*)&orow0[cl] = w0;
        *(float2*)&orow1[cl] = w1;
    }
}

extern "C" void kernel_launch(void* const* d_in, const int* in_sizes, int n_in,
                              void* d_out, int out_size)
{
    const float* x  = (const float*)d_in[0];
    const float* Wq = (const float*)d_in[1];
    const float* Wk = (const float*)d_in[2];
    const float* Wv = (const float*)d_in[3];
    float* out = (float*)d_out;

    dim3 tb(16, 16);
    proj_kernel<<<(B_SZ * T_SEQ) / 64, tb>>>(x, Wq, Wk, Wv);

    flash2<<<dim3(T_SEQ / 64, B_SZ), 128>>>(out);
}

// round 4
// speedup vs baseline: 6.3044x; 1.5519x over previous
#include <cuda_runtime.h>
#include <cuda_fp16.h>
#include <math_constants.h>
#include <cstdint>

#define B_SZ 4
#define T_SEQ 4096
#define C_DIM 768
#define HD 64

// fp16 scratch
__device__ __half g_q[B_SZ * T_SEQ * HD];
__device__ __half g_k[B_SZ * T_SEQ * HD];
__device__ __half g_vt[B_SZ * HD * T_SEQ];        // [b][h][t]
__device__ __half g_wt[3 * HD * C_DIM];           // [m][h][k] fp16 transposed weights

// ---------------------------------------------------------------------------
// Kernel 0: transpose + fp16-convert weights. W[m]: [768][64] -> g_wt[m][h][k].
// grid (12, 3), 256 threads. Tiny.
// ---------------------------------------------------------------------------
__global__ __launch_bounds__(256) void wt_kernel(
    const float* __restrict__ Wq,
    const float* __restrict__ Wk,
    const float* __restrict__ Wv)
{
    __shared__ __half sT[64 * 72];   // [h][kk]
    const int m = blockIdx.y;
    const int k0 = blockIdx.x * 64;
    const float* W = (m == 0) ? Wq : (m == 1) ? Wk : Wv;
    const int tid = threadIdx.x;

    // read 64 k-rows x 64 h, coalesced along h
    #pragma unroll
    for (int u = 0; u < 16; u++) {
        int i = tid + u * 256;
        int kk = i >> 6;
        int h = i & 63;
        sT[h * 72 + kk] = __float2half(W[(size_t)(k0 + kk) * HD + h]);
    }
    __syncthreads();
    // write coalesced rows of g_wt[m][h][k0..k0+63]
    #pragma unroll
    for (int u = 0; u < 2; u++) {
        int i = tid + u * 256;
        int h = i >> 3;
        int c8 = i & 7;
        *(uint4*)&g_wt[(size_t)(m * HD + h) * C_DIM + k0 + c8 * 8] =
            *(const uint4*)&sT[h * 72 + c8 * 8];
    }
}

// ---------------------------------------------------------------------------
// HMMA helper
// ---------------------------------------------------------------------------
__device__ __forceinline__ void mma16816(float c[4],
    uint32_t a0, uint32_t a1, uint32_t a2, uint32_t a3,
    uint32_t b0, uint32_t b1)
{
    asm volatile(
        "mma.sync.aligned.m16n8k16.row.col.f32.f16.f16.f32 "
        "{%0,%1,%2,%3}, {%4,%5,%6,%7}, {%8,%9}, {%0,%1,%2,%3};\n"
        : "+f"(c[0]), "+f"(c[1]), "+f"(c[2]), "+f"(c[3])
        : "r"(a0), "r"(a1), "r"(a2), "r"(a3), "r"(b0), "r"(b1));
}

#define FULLMASK 0xffffffffu
#define PSTR 72

// ---------------------------------------------------------------------------
// Kernel 1: QKV projection with tensor cores.
// BM=128, 768 threads = 24 warps: warp w -> matrix m=w/8, 16-row strip s=w%8.
// K-chunks of 64. x converted fp32->fp16 on load.
// ---------------------------------------------------------------------------
__global__ __launch_bounds__(768) void proj2(const float* __restrict__ x)
{
    __shared__ __half sX[128 * PSTR];       // 18432 B
    __shared__ __half sW[3 * 64 * PSTR];    // 27648 B

    const int tid = threadIdx.x;
    const int warp = tid >> 5;
    const int lane = tid & 31;
    const int g = lane >> 2;
    const int t = lane & 3;
    const int m = warp >> 3;          // 0=q,1=k,2=v
    const int rloc = (warp & 7) * 16; // row strip within 128-row block
    const int row0 = blockIdx.x * 128;

    float acc[8][4];
    #pragma unroll
    for (int nt = 0; nt < 8; nt++)
        #pragma unroll
        for (int c = 0; c < 4; c++) acc[nt][c] = 0.f;

    const float4* x4 = (const float4*)x;

    for (int k0 = 0; k0 < C_DIM; k0 += 64) {
        __syncthreads();
        // x tile: 128 rows x 64 k = 2048 float4
        for (int i = tid; i < 2048; i += 768) {
            int r = i >> 4;
            int k4 = i & 15;
            float4 v = x4[(size_t)(row0 + r) * (C_DIM / 4) + (k0 >> 2) + k4];
            __half2 h0 = __floats2half2_rn(v.x, v.y);
            __half2 h1 = __floats2half2_rn(v.z, v.w);
            __half2* dst = (__half2*)&sX[r * PSTR + k4 * 4];
            dst[0] = h0;
            dst[1] = h1;
        }
        // W tiles: 3*64 rows x 64 k halves = 1536 uint4
        #pragma unroll
        for (int u = 0; u < 2; u++) {
            int i = tid + u * 768;
            int mm = i >> 9;
            int h = (i >> 3) & 63;
            int c8 = i & 7;
            *(uint4*)&sW[(mm * 64 + h) * PSTR + c8 * 8] =
                *(const uint4*)&g_wt[(size_t)(mm * HD + h) * C_DIM + k0 + c8 * 8];
        }
        __syncthreads();

        #pragma unroll
        for (int ks = 0; ks < 4; ks++) {
            int ca = ks * 16 + t * 2;
            uint32_t A0 = *(const uint32_t*)&sX[(rloc + g) * PSTR + ca];
            uint32_t A1 = *(const uint32_t*)&sX[(rloc + g + 8) * PSTR + ca];
            uint32_t A2 = *(const uint32_t*)&sX[(rloc + g) * PSTR + ca + 8];
            uint32_t A3 = *(const uint32_t*)&sX[(rloc + g + 8) * PSTR + ca + 8];
            #pragma unroll
            for (int nt = 0; nt < 8; nt++) {
                uint32_t B0 = *(const uint32_t*)&sW[(m * 64 + nt * 8 + g) * PSTR + ca];
                uint32_t B1 = *(const uint32_t*)&sW[(m * 64 + nt * 8 + g) * PSTR + ca + 8];
                mma16816(acc[nt], A0, A1, A2, A3, B0, B1);
            }
        }
    }

    __syncthreads();   // all warps done reading sX/sW -> safe to reuse

    __half* sVst = sX;   // reinterpret: [h][tloc] with stride 136 (64*136=8704 <= 9216)

    if (m < 2) {
        // direct q/k stores
        __half* dst = (m == 0) ? g_q : g_k;
        int rowg = row0 + rloc + g;
        #pragma unroll
        for (int nt = 0; nt < 8; nt++) {
            int col = nt * 8 + t * 2;
            *(__half2*)&dst[(size_t)rowg * HD + col] =
                __floats2half2_rn(acc[nt][0], acc[nt][1]);
            *(__half2*)&dst[(size_t)(rowg + 8) * HD + col] =
                __floats2half2_rn(acc[nt][2], acc[nt][3]);
        }
    } else {
        // stage v transposed
        #pragma unroll
        for (int nt = 0; nt < 8; nt++) {
            int c = nt * 8 + t * 2;
            sVst[c * 136 + rloc + g]           = __float2half(acc[nt][0]);
            sVst[(c + 1) * 136 + rloc + g]     = __float2half(acc[nt][1]);
            sVst[c * 136 + rloc + g + 8]       = __float2half(acc[nt][2]);
            sVst[(c + 1) * 136 + rloc + g + 8] = __float2half(acc[nt][3]);
        }
    }
    __syncthreads();

    // cooperative v writeout: 64 h rows x 128 t halves = 1024 uint4
    const int bb = row0 >> 12;        // /4096
    const int t0 = row0 & 4095;
    for (int i = tid; i < 1024; i += 768) {
        int h = i >> 4;
        int c8 = i & 15;
        *(uint4*)(g_vt + (size_t)bb * HD * T_SEQ + (size_t)h * T_SEQ + t0 + c8 * 8) =
            *(const uint4*)&sVst[h * 136 + c8 * 8];
    }
}

// ---------------------------------------------------------------------------
// Kernel 2: causal flash attention, col-split warps.
// BM=BN=64, 256 threads = 8 warps: warp = (strip 0..3) x (colhalf 0..1).
// Cross-warp softmax reduction via smem. Heavy tiles first.
// ---------------------------------------------------------------------------
__global__ __launch_bounds__(256) void flash3(float* __restrict__ out)
{
    __shared__ __half sQ[64 * PSTR];
    __shared__ __half sK[64 * PSTR];
    __shared__ __half sVt[64 * PSTR];
    __shared__ __half sP[64 * PSTR];
    __shared__ float sMx[2][64];
    __shared__ float sSum[2][64];

    const int tid = threadIdx.x;
    const int warp = tid >> 5;
    const int lane = tid & 31;
    const int g = lane >> 2;
    const int t = lane & 3;
    const int strip = warp & 3;
    const int ch = warp >> 2;         // column half 0/1
    const int m0 = strip * 16;
    const int iq = (T_SEQ / 64 - 1) - blockIdx.x;
    const int b = blockIdx.y;

    // load Q tile (512 uint4 / 256 threads)
    {
        const uint4* gq = (const uint4*)(g_q + ((size_t)b * T_SEQ + iq * 64) * HD);
        #pragma unroll
        for (int u = 0; u < 2; u++) {
            int i = tid + u * 256;
            int r = i >> 3, c8 = i & 7;
            *(uint4*)&sQ[r * PSTR + c8 * 8] = gq[r * 8 + c8];
        }
    }

    float oc[4][4];
    #pragma unroll
    for (int nt = 0; nt < 4; nt++)
        #pragma unroll
        for (int c = 0; c < 4; c++) oc[nt][c] = 0.f;
    float mr0 = -CUDART_INF_F, mr1 = -CUDART_INF_F;
    float l0 = 0.f, l1 = 0.f;

    const int rA = (m0 + g) * PSTR;
    const int rB = (m0 + g + 8) * PSTR;
    const int row0i = m0 + g;
    const int row1i = m0 + g + 8;

    for (int j = 0; j <= iq; j++) {
        __syncthreads();
        {
            const uint4* gk = (const uint4*)(g_k + ((size_t)b * T_SEQ + j * 64) * HD);
            #pragma unroll
            for (int u = 0; u < 2; u++) {
                int i = tid + u * 256;
                int r = i >> 3, c8 = i & 7;
                *(uint4*)&sK[r * PSTR + c8 * 8] = gk[r * 8 + c8];
            }
            const __half* gvt = g_vt + (size_t)b * HD * T_SEQ + j * 64;
            #pragma unroll
            for (int u = 0; u < 2; u++) {
                int i = tid + u * 256;
                int h = i >> 3, c8 = i & 7;
                *(uint4*)&sVt[h * PSTR + c8 * 8] =
                    *(const uint4*)(gvt + (size_t)h * T_SEQ + c8 * 8);
            }
        }
        __syncthreads();

        // S = Q K^T for this warp's 32 columns
        float sc[4][4];
        #pragma unroll
        for (int nt = 0; nt < 4; nt++)
            #pragma unroll
            for (int c = 0; c < 4; c++) sc[nt][c] = 0.f;

        #pragma unroll
        for (int ks = 0; ks < 4; ks++) {
            int ca = ks * 16 + t * 2;
            uint32_t A0 = *(const uint32_t*)&sQ[rA + ca];
            uint32_t A1 = *(const uint32_t*)&sQ[rB + ca];
            uint32_t A2 = *(const uint32_t*)&sQ[rA + ca + 8];
            uint32_t A3 = *(const uint32_t*)&sQ[rB + ca + 8];
            #pragma unroll
            for (int nt = 0; nt < 4; nt++) {
                int n = ch * 32 + nt * 8;
                uint32_t B0 = *(const uint32_t*)&sK[(n + g) * PSTR + ca];
                uint32_t B1 = *(const uint32_t*)&sK[(n + g) * PSTR + ca + 8];
                mma16816(sc[nt], A0, A1, A2, A3, B0, B1);
            }
        }

        const bool diag = (j == iq);
        float mx0 = -CUDART_INF_F, mx1 = -CUDART_INF_F;
        #pragma unroll
        for (int nt = 0; nt < 4; nt++) {
            int cl = ch * 32 + nt * 8 + t * 2;
            float v0 = sc[nt][0] * 0.125f;
            float v1 = sc[nt][1] * 0.125f;
            float v2 = sc[nt][2] * 0.125f;
            float v3 = sc[nt][3] * 0.125f;
            if (diag) {
                if (cl     > row0i) v0 = -CUDART_INF_F;
                if (cl + 1 > row0i) v1 = -CUDART_INF_F;
                if (cl     > row1i) v2 = -CUDART_INF_F;
                if (cl + 1 > row1i) v3 = -CUDART_INF_F;
            }
            sc[nt][0] = v0; sc[nt][1] = v1; sc[nt][2] = v2; sc[nt][3] = v3;
            mx0 = fmaxf(mx0, fmaxf(v0, v1));
            mx1 = fmaxf(mx1, fmaxf(v2, v3));
        }
        mx0 = fmaxf(mx0, __shfl_xor_sync(FULLMASK, mx0, 1));
        mx0 = fmaxf(mx0, __shfl_xor_sync(FULLMASK, mx0, 2));
        mx1 = fmaxf(mx1, __shfl_xor_sync(FULLMASK, mx1, 1));
        mx1 = fmaxf(mx1, __shfl_xor_sync(FULLMASK, mx1, 2));
        if (t == 0) {
            sMx[ch][row0i] = mx0;
            sMx[ch][row1i] = mx1;
        }
        __syncthreads();
        float mn0 = fmaxf(mr0, fmaxf(sMx[0][row0i], sMx[1][row0i]));
        float mn1 = fmaxf(mr1, fmaxf(sMx[0][row1i], sMx[1][row1i]));
        float al0 = __expf(mr0 - mn0);
        float al1 = __expf(mr1 - mn1);
        float s0 = 0.f, s1 = 0.f;
        #pragma unroll
        for (int nt = 0; nt < 4; nt++) {
            int cl = ch * 32 + nt * 8 + t * 2;
            float p0 = __expf(sc[nt][0] - mn0);
            float p1 = __expf(sc[nt][1] - mn0);
            float p2 = __expf(sc[nt][2] - mn1);
            float p3 = __expf(sc[nt][3] - mn1);
            s0 += p0 + p1;
            s1 += p2 + p3;
            *(__half2*)&sP[rA + cl] = __floats2half2_rn(p0, p1);
            *(__half2*)&sP[rB + cl] = __floats2half2_rn(p2, p3);
        }
        s0 += __shfl_xor_sync(FULLMASK, s0, 1);
        s0 += __shfl_xor_sync(FULLMASK, s0, 2);
        s1 += __shfl_xor_sync(FULLMASK, s1, 1);
        s1 += __shfl_xor_sync(FULLMASK, s1, 2);
        if (t == 0) {
            sSum[ch][row0i] = s0;
            sSum[ch][row1i] = s1;
        }
        __syncthreads();
        float st0 = sSum[0][row0i] + sSum[1][row0i];
        float st1 = sSum[0][row1i] + sSum[1][row1i];
        l0 = l0 * al0 + st0;
        l1 = l1 * al1 + st1;
        mr0 = mn0;
        mr1 = mn1;
        #pragma unroll
        for (int nt = 0; nt < 4; nt++) {
            oc[nt][0] *= al0;
            oc[nt][1] *= al0;
            oc[nt][2] *= al1;
            oc[nt][3] *= al1;
        }

        // O += P V : this warp computes its 32 output columns using all 64 s
        #pragma unroll
        for (int ks = 0; ks < 4; ks++) {
            int ca = ks * 16 + t * 2;
            uint32_t A0 = *(const uint32_t*)&sP[rA + ca];
            uint32_t A1 = *(const uint32_t*)&sP[rB + ca];
            uint32_t A2 = *(const uint32_t*)&sP[rA + ca + 8];
            uint32_t A3 = *(const uint32_t*)&sP[rB + ca + 8];
            #pragma unroll
            for (int nt = 0; nt < 4; nt++) {
                int h = ch * 32 + nt * 8;
                uint32_t B0 = *(const uint32_t*)&sVt[(h + g) * PSTR + ca];
                uint32_t B1 = *(const uint32_t*)&sVt[(h + g) * PSTR + ca + 8];
                mma16816(oc[nt], A0, A1, A2, A3, B0, B1);
            }
        }
    }

    // epilogue
    float inv0 = 1.f / l0;
    float inv1 = 1.f / l1;
    float* orow0 = out + ((size_t)b * T_SEQ + iq * 64 + m0 + g) * HD;
    float* orow1 = orow0 + (size_t)8 * HD;
    #pragma unroll
    for (int nt = 0; nt < 4; nt++) {
        int cl = ch * 32 + nt * 8 + t * 2;
        *(float2*)&orow0[cl] = make_float2(oc[nt][0] * inv0, oc[nt][1] * inv0);
        *(float2*)&orow1[cl] = make_float2(oc[nt][2] * inv1, oc[nt][3] * inv1);
    }
}

extern "C" void kernel_launch(void* const* d_in, const int* in_sizes, int n_in,
                              void* d_out, int out_size)
{
    const float* x  = (const float*)d_in[0];
    const float* Wq = (const float*)d_in[1];
    const float* Wk = (const float*)d_in[2];
    const float* Wv = (const float*)d_in[3];
    float* out = (float*)d_out;

    wt_kernel<<<dim3(C_DIM / 64, 3), 256>>>(Wq, Wk, Wv);
    proj2<<<(B_SZ * T_SEQ) / 128, 768>>>(x);
    flash3<<<dim3(T_SEQ / 64, B_SZ), 256>>>(out);
}

// round 5
// speedup vs baseline: 8.4143x; 1.3347x over previous
#include <cuda_runtime.h>
#include <cuda_fp16.h>
#include <math_constants.h>
#include <cstdint>

#define B_SZ 4
#define T_SEQ 4096
#define C_DIM 768
#define HD 64

// fp16 scratch
__device__ __half g_q[B_SZ * T_SEQ * HD];
__device__ __half g_k[B_SZ * T_SEQ * HD];
__device__ __half g_vt[B_SZ * HD * T_SEQ];        // [b][h][t]
__device__ __half g_wt[3 * HD * C_DIM];           // [m][h][k] fp16 transposed weights

#define SCALE_Q 0.1803368801111244f   // 0.125 * log2(e): folds softmax scale + exp2 base

// ---------------------------------------------------------------------------
// Kernel 0: transpose + fp16-convert weights; Wq pre-scaled by 0.125*log2e.
// ---------------------------------------------------------------------------
__global__ __launch_bounds__(256) void wt_kernel(
    const float* __restrict__ Wq,
    const float* __restrict__ Wk,
    const float* __restrict__ Wv)
{
    __shared__ __half sT[64 * 72];
    const int m = blockIdx.y;
    const int k0 = blockIdx.x * 64;
    const float* W = (m == 0) ? Wq : (m == 1) ? Wk : Wv;
    const float scl = (m == 0) ? SCALE_Q : 1.0f;
    const int tid = threadIdx.x;

    #pragma unroll
    for (int u = 0; u < 16; u++) {
        int i = tid + u * 256;
        int kk = i >> 6;
        int h = i & 63;
        sT[h * 72 + kk] = __float2half(W[(size_t)(k0 + kk) * HD + h] * scl);
    }
    __syncthreads();
    #pragma unroll
    for (int u = 0; u < 2; u++) {
        int i = tid + u * 256;
        int h = i >> 3;
        int c8 = i & 7;
        *(uint4*)&g_wt[(size_t)(m * HD + h) * C_DIM + k0 + c8 * 8] =
            *(const uint4*)&sT[h * 72 + c8 * 8];
    }
}

// ---------------------------------------------------------------------------
// helpers
// ---------------------------------------------------------------------------
__device__ __forceinline__ void mma16816(float c[4],
    uint32_t a0, uint32_t a1, uint32_t a2, uint32_t a3,
    uint32_t b0, uint32_t b1)
{
    asm volatile(
        "mma.sync.aligned.m16n8k16.row.col.f32.f16.f16.f32 "
        "{%0,%1,%2,%3}, {%4,%5,%6,%7}, {%8,%9}, {%0,%1,%2,%3};\n"
        : "+f"(c[0]), "+f"(c[1]), "+f"(c[2]), "+f"(c[3])
        : "r"(a0), "r"(a1), "r"(a2), "r"(a3), "r"(b0), "r"(b1));
}

__device__ __forceinline__ float ex2(float x)
{
    float y;
    asm("ex2.approx.f32 %0, %1;" : "=f"(y) : "f"(x));
    return y;
}

__device__ __forceinline__ void cp_async16(void* dst, const void* src)
{
    uint32_t s = (uint32_t)__cvta_generic_to_shared(dst);
    asm volatile("cp.async.cg.shared.global [%0], [%1], 16;\n" :: "r"(s), "l"(src));
}
#define CP_COMMIT() asm volatile("cp.async.commit_group;\n")
#define CP_WAIT1()  asm volatile("cp.async.wait_group 1;\n")
#define CP_WAIT0()  asm volatile("cp.async.wait_group 0;\n")

#define FULLMASK 0xffffffffu
#define PSTR 72

// ---------------------------------------------------------------------------
// Kernel 1: QKV projection with tensor cores (unchanged from R4).
// ---------------------------------------------------------------------------
__global__ __launch_bounds__(768) void proj2(const float* __restrict__ x)
{
    __shared__ __half sX[128 * PSTR];
    __shared__ __half sW[3 * 64 * PSTR];

    const int tid = threadIdx.x;
    const int warp = tid >> 5;
    const int lane = tid & 31;
    const int g = lane >> 2;
    const int t = lane & 3;
    const int m = warp >> 3;
    const int rloc = (warp & 7) * 16;
    const int row0 = blockIdx.x * 128;

    float acc[8][4];
    #pragma unroll
    for (int nt = 0; nt < 8; nt++)
        #pragma unroll
        for (int c = 0; c < 4; c++) acc[nt][c] = 0.f;

    const float4* x4 = (const float4*)x;

    for (int k0 = 0; k0 < C_DIM; k0 += 64) {
        __syncthreads();
        for (int i = tid; i < 2048; i += 768) {
            int r = i >> 4;
            int k4 = i & 15;
            float4 v = x4[(size_t)(row0 + r) * (C_DIM / 4) + (k0 >> 2) + k4];
            __half2 h0 = __floats2half2_rn(v.x, v.y);
            __half2 h1 = __floats2half2_rn(v.z, v.w);
            __half2* dst = (__half2*)&sX[r * PSTR + k4 * 4];
            dst[0] = h0;
            dst[1] = h1;
        }
        #pragma unroll
        for (int u = 0; u < 2; u++) {
            int i = tid + u * 768;
            int mm = i >> 9;
            int h = (i >> 3) & 63;
            int c8 = i & 7;
            *(uint4*)&sW[(mm * 64 + h) * PSTR + c8 * 8] =
                *(const uint4*)&g_wt[(size_t)(mm * HD + h) * C_DIM + k0 + c8 * 8];
        }
        __syncthreads();

        #pragma unroll
        for (int ks = 0; ks < 4; ks++) {
            int ca = ks * 16 + t * 2;
            uint32_t A0 = *(const uint32_t*)&sX[(rloc + g) * PSTR + ca];
            uint32_t A1 = *(const uint32_t*)&sX[(rloc + g + 8) * PSTR + ca];
            uint32_t A2 = *(const uint32_t*)&sX[(rloc + g) * PSTR + ca + 8];
            uint32_t A3 = *(const uint32_t*)&sX[(rloc + g + 8) * PSTR + ca + 8];
            #pragma unroll
            for (int nt = 0; nt < 8; nt++) {
                uint32_t B0 = *(const uint32_t*)&sW[(m * 64 + nt * 8 + g) * PSTR + ca];
                uint32_t B1 = *(const uint32_t*)&sW[(m * 64 + nt * 8 + g) * PSTR + ca + 8];
                mma16816(acc[nt], A0, A1, A2, A3, B0, B1);
            }
        }
    }

    __syncthreads();

    __half* sVst = sX;   // reuse: [h][tloc] stride 136

    if (m < 2) {
        __half* dst = (m == 0) ? g_q : g_k;
        int rowg = row0 + rloc + g;
        #pragma unroll
        for (int nt = 0; nt < 8; nt++) {
            int col = nt * 8 + t * 2;
            *(__half2*)&dst[(size_t)rowg * HD + col] =
                __floats2half2_rn(acc[nt][0], acc[nt][1]);
            *(__half2*)&dst[(size_t)(rowg + 8) * HD + col] =
                __floats2half2_rn(acc[nt][2], acc[nt][3]);
        }
    } else {
        #pragma unroll
        for (int nt = 0; nt < 8; nt++) {
            int c = nt * 8 + t * 2;
            sVst[c * 136 + rloc + g]           = __float2half(acc[nt][0]);
            sVst[(c + 1) * 136 + rloc + g]     = __float2half(acc[nt][1]);
            sVst[c * 136 + rloc + g + 8]       = __float2half(acc[nt][2]);
            sVst[(c + 1) * 136 + rloc + g + 8] = __float2half(acc[nt][3]);
        }
    }
    __syncthreads();

    const int bb = row0 >> 12;
    const int t0 = row0 & 4095;
    for (int i = tid; i < 1024; i += 768) {
        int h = i >> 4;
        int c8 = i & 15;
        *(uint4*)(g_vt + (size_t)bb * HD * T_SEQ + (size_t)h * T_SEQ + t0 + c8 * 8) =
            *(const uint4*)&sVst[h * 136 + c8 * 8];
    }
}

// ---------------------------------------------------------------------------
// Kernel 2: flash attention. 4 warps x 16 rows x 64 cols. P in registers.
// Double-buffered K/V via cp.async. S pre-scaled to log2 domain (Wq folded).
// ---------------------------------------------------------------------------
__global__ __launch_bounds__(128) void flash4(float* __restrict__ out)
{
    __shared__ __half sQ[64 * PSTR];
    __shared__ __half sK[2][64 * PSTR];
    __shared__ __half sVt[2][64 * PSTR];

    const int tid = threadIdx.x;
    const int warp = tid >> 5;
    const int lane = tid & 31;
    const int g = lane >> 2;
    const int t = lane & 3;
    const int m0 = warp * 16;
    const int iq = (T_SEQ / 64 - 1) - blockIdx.x;   // heavy-first
    const int b = blockIdx.y;

    const __half* gk_base = g_k + (size_t)b * T_SEQ * HD;
    const __half* gvt_base = g_vt + (size_t)b * HD * T_SEQ;

    // Q tile load (plain)
    {
        const uint4* gq = (const uint4*)(g_q + ((size_t)b * T_SEQ + iq * 64) * HD);
        #pragma unroll
        for (int u = 0; u < 4; u++) {
            int i = tid + u * 128;
            int r = i >> 3, c8 = i & 7;
            *(uint4*)&sQ[r * PSTR + c8 * 8] = gq[r * 8 + c8];
        }
    }

    // async load of tile j into buffer d
    auto loadKV = [&](int j, int d) {
        #pragma unroll
        for (int u = 0; u < 4; u++) {
            int i = tid + u * 128;
            int r = i >> 3, c8 = i & 7;
            cp_async16(&sK[d][r * PSTR + c8 * 8],
                       gk_base + ((size_t)(j * 64 + r) * HD) + c8 * 8);
        }
        #pragma unroll
        for (int u = 0; u < 4; u++) {
            int i = tid + u * 128;
            int h = i >> 3, c8 = i & 7;
            cp_async16(&sVt[d][h * PSTR + c8 * 8],
                       gvt_base + (size_t)h * T_SEQ + j * 64 + c8 * 8);
        }
    };

    loadKV(0, 0);
    CP_COMMIT();

    float oc[8][4];
    #pragma unroll
    for (int nt = 0; nt < 8; nt++)
        #pragma unroll
        for (int c = 0; c < 4; c++) oc[nt][c] = 0.f;
    float mr0 = -CUDART_INF_F, mr1 = -CUDART_INF_F;
    float l0 = 0.f, l1 = 0.f;

    const int rA = (m0 + g) * PSTR;
    const int rB = (m0 + g + 8) * PSTR;
    const int row0i = m0 + g;
    const int row1i = m0 + g + 8;

    for (int j = 0; j <= iq; j++) {
        const int cur = j & 1;
        __syncthreads();                 // prior reads of buf cur^1 complete
        if (j < iq) {
            loadKV(j + 1, cur ^ 1);
            CP_COMMIT();
            CP_WAIT1();                  // tile j landed
        } else {
            CP_WAIT0();
        }
        __syncthreads();

        const __half* bK = sK[cur];
        const __half* bV = sVt[cur];

        // S = Q K^T (pre-scaled, log2 domain)
        float sc[8][4];
        #pragma unroll
        for (int nt = 0; nt < 8; nt++)
            #pragma unroll
            for (int c = 0; c < 4; c++) sc[nt][c] = 0.f;

        #pragma unroll
        for (int ks = 0; ks < 4; ks++) {
            int ca = ks * 16 + t * 2;
            uint32_t A0 = *(const uint32_t*)&sQ[rA + ca];
            uint32_t A1 = *(const uint32_t*)&sQ[rB + ca];
            uint32_t A2 = *(const uint32_t*)&sQ[rA + ca + 8];
            uint32_t A3 = *(const uint32_t*)&sQ[rB + ca + 8];
            #pragma unroll
            for (int nt = 0; nt < 8; nt++) {
                uint32_t B0 = *(const uint32_t*)&bK[(nt * 8 + g) * PSTR + ca];
                uint32_t B1 = *(const uint32_t*)&bK[(nt * 8 + g) * PSTR + ca + 8];
                mma16816(sc[nt], A0, A1, A2, A3, B0, B1);
            }
        }

        // causal mask on diagonal tile
        if (j == iq) {
            #pragma unroll
            for (int nt = 0; nt < 8; nt++) {
                int cl = nt * 8 + t * 2;
                if (cl     > row0i) sc[nt][0] = -CUDART_INF_F;
                if (cl + 1 > row0i) sc[nt][1] = -CUDART_INF_F;
                if (cl     > row1i) sc[nt][2] = -CUDART_INF_F;
                if (cl + 1 > row1i) sc[nt][3] = -CUDART_INF_F;
            }
        }

        // online softmax (log2 domain)
        float mx0 = -CUDART_INF_F, mx1 = -CUDART_INF_F;
        #pragma unroll
        for (int nt = 0; nt < 8; nt++) {
            mx0 = fmaxf(mx0, fmaxf(sc[nt][0], sc[nt][1]));
            mx1 = fmaxf(mx1, fmaxf(sc[nt][2], sc[nt][3]));
        }
        mx0 = fmaxf(mx0, __shfl_xor_sync(FULLMASK, mx0, 1));
        mx0 = fmaxf(mx0, __shfl_xor_sync(FULLMASK, mx0, 2));
        mx1 = fmaxf(mx1, __shfl_xor_sync(FULLMASK, mx1, 1));
        mx1 = fmaxf(mx1, __shfl_xor_sync(FULLMASK, mx1, 2));

        float mn0 = fmaxf(mr0, mx0);
        float mn1 = fmaxf(mr1, mx1);
        float al0 = ex2(mr0 - mn0);
        float al1 = ex2(mr1 - mn1);

        uint32_t pa[4][4];   // PV A-fragments, packed in-register
        float s0 = 0.f, s1 = 0.f;
        #pragma unroll
        for (int nt = 0; nt < 8; nt++) {
            float p0 = ex2(sc[nt][0] - mn0);
            float p1 = ex2(sc[nt][1] - mn0);
            float p2 = ex2(sc[nt][2] - mn1);
            float p3 = ex2(sc[nt][3] - mn1);
            s0 += p0 + p1;
            s1 += p2 + p3;
            __half2 h01 = __floats2half2_rn(p0, p1);
            __half2 h23 = __floats2half2_rn(p2, p3);
            int ks = nt >> 1;
            if ((nt & 1) == 0) {
                pa[ks][0] = *(uint32_t*)&h01;
                pa[ks][1] = *(uint32_t*)&h23;
            } else {
                pa[ks][2] = *(uint32_t*)&h01;
                pa[ks][3] = *(uint32_t*)&h23;
            }
        }
        s0 += __shfl_xor_sync(FULLMASK, s0, 1);
        s0 += __shfl_xor_sync(FULLMASK, s0, 2);
        s1 += __shfl_xor_sync(FULLMASK, s1, 1);
        s1 += __shfl_xor_sync(FULLMASK, s1, 2);
        l0 = l0 * al0 + s0;
        l1 = l1 * al1 + s1;
        mr0 = mn0;
        mr1 = mn1;
        #pragma unroll
        for (int nt = 0; nt < 8; nt++) {
            oc[nt][0] *= al0;
            oc[nt][1] *= al0;
            oc[nt][2] *= al1;
            oc[nt][3] *= al1;
        }

        // O += P V (A from registers)
        #pragma unroll
        for (int ks = 0; ks < 4; ks++) {
            int ca = ks * 16 + t * 2;
            #pragma unroll
            for (int nt = 0; nt < 8; nt++) {
                uint32_t B0 = *(const uint32_t*)&bV[(nt * 8 + g) * PSTR + ca];
                uint32_t B1 = *(const uint32_t*)&bV[(nt * 8 + g) * PSTR + ca + 8];
                mma16816(oc[nt], pa[ks][0], pa[ks][1], pa[ks][2], pa[ks][3], B0, B1);
            }
        }
    }

    // epilogue
    float inv0 = 1.f / l0;
    float inv1 = 1.f / l1;
    float* orow0 = out + ((size_t)b * T_SEQ + iq * 64 + m0 + g) * HD;
    float* orow1 = orow0 + (size_t)8 * HD;
    #pragma unroll
    for (int nt = 0; nt < 8; nt++) {
        int cl = nt * 8 + t * 2;
        *(float2*)&orow0[cl] = make_float2(oc[nt][0] * inv0, oc[nt][1] * inv0);
        *(float2*)&orow1[cl] = make_float2(oc[nt][2] * inv1, oc[nt][3] * inv1);
    }
}

extern "C" void kernel_launch(void* const* d_in, const int* in_sizes, int n_in,
                              void* d_out, int out_size)
{
    const float* x  = (const float*)d_in[0];
    const float* Wq = (const float*)d_in[1];
    const float* Wk = (const float*)d_in[2];
    const float* Wv = (const float*)d_in[3];
    float* out = (float*)d_out;

    wt_kernel<<<dim3(C_DIM / 64, 3), 256>>>(Wq, Wk, Wv);
    proj2<<<(B_SZ * T_SEQ) / 128, 768>>>(x);
    flash4<<<dim3(T_SEQ / 64, B_SZ), 128>>>(out);
}

// round 6
// speedup vs baseline: 9.3768x; 1.1144x over previous
#include <cuda_runtime.h>
#include <cuda_fp16.h>
#include <math_constants.h>
#include <cstdint>

#define B_SZ 4
#define T_SEQ 4096
#define C_DIM 768
#define HD 64
#define NCHUNK 2

// fp16 scratch
__device__ __half g_q[B_SZ * T_SEQ * HD];
__device__ __half g_k[B_SZ * T_SEQ * HD];
__device__ __half g_vt[B_SZ * HD * T_SEQ];        // [b][h][t]
__device__ __half g_wt[3 * HD * C_DIM];           // [m][h][k]

// split-KV partials
__device__ float g_po[NCHUNK * B_SZ * T_SEQ * HD];   // unnormalized O
__device__ float g_pm[NCHUNK * B_SZ * T_SEQ];        // row max (log2 domain)
__device__ float g_pl[NCHUNK * B_SZ * T_SEQ];        // row sum

#define SCALE_Q 0.1803368801111244f   // 0.125 * log2(e)

// ---------------------------------------------------------------------------
// Kernel 0: transpose + fp16-convert weights; Wq pre-scaled.
// ---------------------------------------------------------------------------
__global__ __launch_bounds__(256) void wt_kernel(
    const float* __restrict__ Wq,
    const float* __restrict__ Wk,
    const float* __restrict__ Wv)
{
    __shared__ __half sT[64 * 72];
    const int m = blockIdx.y;
    const int k0 = blockIdx.x * 64;
    const float* W = (m == 0) ? Wq : (m == 1) ? Wk : Wv;
    const float scl = (m == 0) ? SCALE_Q : 1.0f;
    const int tid = threadIdx.x;

    #pragma unroll
    for (int u = 0; u < 16; u++) {
        int i = tid + u * 256;
        int kk = i >> 6;
        int h = i & 63;
        sT[h * 72 + kk] = __float2half(W[(size_t)(k0 + kk) * HD + h] * scl);
    }
    __syncthreads();
    #pragma unroll
    for (int u = 0; u < 2; u++) {
        int i = tid + u * 256;
        int h = i >> 3;
        int c8 = i & 7;
        *(uint4*)&g_wt[(size_t)(m * HD + h) * C_DIM + k0 + c8 * 8] =
            *(const uint4*)&sT[h * 72 + c8 * 8];
    }
}

// ---------------------------------------------------------------------------
// helpers
// ---------------------------------------------------------------------------
__device__ __forceinline__ void mma16816(float c[4],
    uint32_t a0, uint32_t a1, uint32_t a2, uint32_t a3,
    uint32_t b0, uint32_t b1)
{
    asm volatile(
        "mma.sync.aligned.m16n8k16.row.col.f32.f16.f16.f32 "
        "{%0,%1,%2,%3}, {%4,%5,%6,%7}, {%8,%9}, {%0,%1,%2,%3};\n"
        : "+f"(c[0]), "+f"(c[1]), "+f"(c[2]), "+f"(c[3])
        : "r"(a0), "r"(a1), "r"(a2), "r"(a3), "r"(b0), "r"(b1));
}

__device__ __forceinline__ float ex2(float x)
{
    float y;
    asm("ex2.approx.f32 %0, %1;" : "=f"(y) : "f"(x));
    return y;
}

__device__ __forceinline__ void cp_async16(void* dst, const void* src)
{
    uint32_t s = (uint32_t)__cvta_generic_to_shared(dst);
    asm volatile("cp.async.cg.shared.global [%0], [%1], 16;\n" :: "r"(s), "l"(src));
}
#define CP_COMMIT() asm volatile("cp.async.commit_group;\n")
#define CP_WAIT1()  asm volatile("cp.async.wait_group 1;\n")
#define CP_WAIT0()  asm volatile("cp.async.wait_group 0;\n")

#define FULLMASK 0xffffffffu
#define PSTR 72

// ---------------------------------------------------------------------------
// Kernel 1: QKV projection with tensor cores.
// ---------------------------------------------------------------------------
__global__ __launch_bounds__(768) void proj2(const float* __restrict__ x)
{
    __shared__ __half sX[128 * PSTR];
    __shared__ __half sW[3 * 64 * PSTR];

    const int tid = threadIdx.x;
    const int warp = tid >> 5;
    const int lane = tid & 31;
    const int g = lane >> 2;
    const int t = lane & 3;
    const int m = warp >> 3;
    const int rloc = (warp & 7) * 16;
    const int row0 = blockIdx.x * 128;

    float acc[8][4];
    #pragma unroll
    for (int nt = 0; nt < 8; nt++)
        #pragma unroll
        for (int c = 0; c < 4; c++) acc[nt][c] = 0.f;

    const float4* x4 = (const float4*)x;

    for (int k0 = 0; k0 < C_DIM; k0 += 64) {
        __syncthreads();
        for (int i = tid; i < 2048; i += 768) {
            int r = i >> 4;
            int k4 = i & 15;
            float4 v = x4[(size_t)(row0 + r) * (C_DIM / 4) + (k0 >> 2) + k4];
            __half2 h0 = __floats2half2_rn(v.x, v.y);
            __half2 h1 = __floats2half2_rn(v.z, v.w);
            __half2* dst = (__half2*)&sX[r * PSTR + k4 * 4];
            dst[0] = h0;
            dst[1] = h1;
        }
        #pragma unroll
        for (int u = 0; u < 2; u++) {
            int i = tid + u * 768;
            int mm = i >> 9;
            int h = (i >> 3) & 63;
            int c8 = i & 7;
            *(uint4*)&sW[(mm * 64 + h) * PSTR + c8 * 8] =
                *(const uint4*)&g_wt[(size_t)(mm * HD + h) * C_DIM + k0 + c8 * 8];
        }
        __syncthreads();

        #pragma unroll
        for (int ks = 0; ks < 4; ks++) {
            int ca = ks * 16 + t * 2;
            uint32_t A0 = *(const uint32_t*)&sX[(rloc + g) * PSTR + ca];
            uint32_t A1 = *(const uint32_t*)&sX[(rloc + g + 8) * PSTR + ca];
            uint32_t A2 = *(const uint32_t*)&sX[(rloc + g) * PSTR + ca + 8];
            uint32_t A3 = *(const uint32_t*)&sX[(rloc + g + 8) * PSTR + ca + 8];
            #pragma unroll
            for (int nt = 0; nt < 8; nt++) {
                uint32_t B0 = *(const uint32_t*)&sW[(m * 64 + nt * 8 + g) * PSTR + ca];
                uint32_t B1 = *(const uint32_t*)&sW[(m * 64 + nt * 8 + g) * PSTR + ca + 8];
                mma16816(acc[nt], A0, A1, A2, A3, B0, B1);
            }
        }
    }

    __syncthreads();

    __half* sVst = sX;   // reuse: [h][tloc] stride 136

    if (m < 2) {
        __half* dst = (m == 0) ? g_q : g_k;
        int rowg = row0 + rloc + g;
        #pragma unroll
        for (int nt = 0; nt < 8; nt++) {
            int col = nt * 8 + t * 2;
            *(__half2*)&dst[(size_t)rowg * HD + col] =
                __floats2half2_rn(acc[nt][0], acc[nt][1]);
            *(__half2*)&dst[(size_t)(rowg + 8) * HD + col] =
                __floats2half2_rn(acc[nt][2], acc[nt][3]);
        }
    } else {
        #pragma unroll
        for (int nt = 0; nt < 8; nt++) {
            int c = nt * 8 + t * 2;
            sVst[c * 136 + rloc + g]           = __float2half(acc[nt][0]);
            sVst[(c + 1) * 136 + rloc + g]     = __float2half(acc[nt][1]);
            sVst[c * 136 + rloc + g + 8]       = __float2half(acc[nt][2]);
            sVst[(c + 1) * 136 + rloc + g + 8] = __float2half(acc[nt][3]);
        }
    }
    __syncthreads();

    const int bb = row0 >> 12;
    const int t0 = row0 & 4095;
    for (int i = tid; i < 1024; i += 768) {
        int h = i >> 4;
        int c8 = i & 15;
        *(uint4*)(g_vt + (size_t)bb * HD * T_SEQ + (size_t)h * T_SEQ + t0 + c8 * 8) =
            *(const uint4*)&sVst[h * 136 + c8 * 8];
    }
}

// ---------------------------------------------------------------------------
// Kernel 2: split-KV flash attention. Grid (64, NCHUNK, B).
// Chunk c handles KV tiles j = c, c+2, ... <= iq. Partials to g_po/g_pm/g_pl.
// ---------------------------------------------------------------------------
__global__ __launch_bounds__(128) void flash5()
{
    __shared__ __half sQ[64 * PSTR];
    __shared__ __half sK[2][64 * PSTR];
    __shared__ __half sVt[2][64 * PSTR];

    const int tid = threadIdx.x;
    const int warp = tid >> 5;
    const int lane = tid & 31;
    const int g = lane >> 2;
    const int t = lane & 3;
    const int m0 = warp * 16;
    const int iq = (T_SEQ / 64 - 1) - blockIdx.x;   // heavy-first
    const int chunk = blockIdx.y;
    const int b = blockIdx.z;

    const __half* gk_base = g_k + (size_t)b * T_SEQ * HD;
    const __half* gvt_base = g_vt + (size_t)b * HD * T_SEQ;

    {
        const uint4* gq = (const uint4*)(g_q + ((size_t)b * T_SEQ + iq * 64) * HD);
        #pragma unroll
        for (int u = 0; u < 4; u++) {
            int i = tid + u * 128;
            int r = i >> 3, c8 = i & 7;
            *(uint4*)&sQ[r * PSTR + c8 * 8] = gq[r * 8 + c8];
        }
    }

    auto loadKV = [&](int j, int d) {
        #pragma unroll
        for (int u = 0; u < 4; u++) {
            int i = tid + u * 128;
            int r = i >> 3, c8 = i & 7;
            cp_async16(&sK[d][r * PSTR + c8 * 8],
                       gk_base + ((size_t)(j * 64 + r) * HD) + c8 * 8);
        }
        #pragma unroll
        for (int u = 0; u < 4; u++) {
            int i = tid + u * 128;
            int h = i >> 3, c8 = i & 7;
            cp_async16(&sVt[d][h * PSTR + c8 * 8],
                       gvt_base + (size_t)h * T_SEQ + j * 64 + c8 * 8);
        }
    };

    float oc[8][4];
    #pragma unroll
    for (int nt = 0; nt < 8; nt++)
        #pragma unroll
        for (int c = 0; c < 4; c++) oc[nt][c] = 0.f;
    float mr0 = -CUDART_INF_F, mr1 = -CUDART_INF_F;
    float l0 = 0.f, l1 = 0.f;

    const int rA = (m0 + g) * PSTR;
    const int rB = (m0 + g + 8) * PSTR;
    const int row0i = m0 + g;
    const int row1i = m0 + g + 8;

    if (chunk <= iq) {
        loadKV(chunk, 0);
        CP_COMMIT();
    }

    int d = 0;
    for (int j = chunk; j <= iq; j += NCHUNK) {
        __syncthreads();
        if (j + NCHUNK <= iq) {
            loadKV(j + NCHUNK, d ^ 1);
            CP_COMMIT();
            CP_WAIT1();
        } else {
            CP_WAIT0();
        }
        __syncthreads();

        const __half* bK = sK[d];
        const __half* bV = sVt[d];

        float sc[8][4];
        #pragma unroll
        for (int nt = 0; nt < 8; nt++)
            #pragma unroll
            for (int c = 0; c < 4; c++) sc[nt][c] = 0.f;

        #pragma unroll
        for (int ks = 0; ks < 4; ks++) {
            int ca = ks * 16 + t * 2;
            uint32_t A0 = *(const uint32_t*)&sQ[rA + ca];
            uint32_t A1 = *(const uint32_t*)&sQ[rB + ca];
            uint32_t A2 = *(const uint32_t*)&sQ[rA + ca + 8];
            uint32_t A3 = *(const uint32_t*)&sQ[rB + ca + 8];
            #pragma unroll
            for (int nt = 0; nt < 8; nt++) {
                uint32_t B0 = *(const uint32_t*)&bK[(nt * 8 + g) * PSTR + ca];
                uint32_t B1 = *(const uint32_t*)&bK[(nt * 8 + g) * PSTR + ca + 8];
                mma16816(sc[nt], A0, A1, A2, A3, B0, B1);
            }
        }

        if (j == iq) {
            #pragma unroll
            for (int nt = 0; nt < 8; nt++) {
                int cl = nt * 8 + t * 2;
                if (cl     > row0i) sc[nt][0] = -CUDART_INF_F;
                if (cl + 1 > row0i) sc[nt][1] = -CUDART_INF_F;
                if (cl     > row1i) sc[nt][2] = -CUDART_INF_F;
                if (cl + 1 > row1i) sc[nt][3] = -CUDART_INF_F;
            }
        }

        float mx0 = -CUDART_INF_F, mx1 = -CUDART_INF_F;
        #pragma unroll
        for (int nt = 0; nt < 8; nt++) {
            mx0 = fmaxf(mx0, fmaxf(sc[nt][0], sc[nt][1]));
            mx1 = fmaxf(mx1, fmaxf(sc[nt][2], sc[nt][3]));
        }
        mx0 = fmaxf(mx0, __shfl_xor_sync(FULLMASK, mx0, 1));
        mx0 = fmaxf(mx0, __shfl_xor_sync(FULLMASK, mx0, 2));
        mx1 = fmaxf(mx1, __shfl_xor_sync(FULLMASK, mx1, 1));
        mx1 = fmaxf(mx1, __shfl_xor_sync(FULLMASK, mx1, 2));

        float mn0 = fmaxf(mr0, mx0);
        float mn1 = fmaxf(mr1, mx1);
        float al0 = ex2(mr0 - mn0);
        float al1 = ex2(mr1 - mn1);

        uint32_t pa[4][4];
        float s0 = 0.f, s1 = 0.f;
        #pragma unroll
        for (int nt = 0; nt < 8; nt++) {
            float p0 = ex2(sc[nt][0] - mn0);
            float p1 = ex2(sc[nt][1] - mn0);
            float p2 = ex2(sc[nt][2] - mn1);
            float p3 = ex2(sc[nt][3] - mn1);
            s0 += p0 + p1;
            s1 += p2 + p3;
            __half2 h01 = __floats2half2_rn(p0, p1);
            __half2 h23 = __floats2half2_rn(p2, p3);
            int ks = nt >> 1;
            if ((nt & 1) == 0) {
                pa[ks][0] = *(uint32_t*)&h01;
                pa[ks][1] = *(uint32_t*)&h23;
            } else {
                pa[ks][2] = *(uint32_t*)&h01;
                pa[ks][3] = *(uint32_t*)&h23;
            }
        }
        s0 += __shfl_xor_sync(FULLMASK, s0, 1);
        s0 += __shfl_xor_sync(FULLMASK, s0, 2);
        s1 += __shfl_xor_sync(FULLMASK, s1, 1);
        s1 += __shfl_xor_sync(FULLMASK, s1, 2);
        l0 = l0 * al0 + s0;
        l1 = l1 * al1 + s1;
        mr0 = mn0;
        mr1 = mn1;
        #pragma unroll
        for (int nt = 0; nt < 8; nt++) {
            oc[nt][0] *= al0;
            oc[nt][1] *= al0;
            oc[nt][2] *= al1;
            oc[nt][3] *= al1;
        }

        #pragma unroll
        for (int ks = 0; ks < 4; ks++) {
            int ca = ks * 16 + t * 2;
            #pragma unroll
            for (int nt = 0; nt < 8; nt++) {
                uint32_t B0 = *(const uint32_t*)&bV[(nt * 8 + g) * PSTR + ca];
                uint32_t B1 = *(const uint32_t*)&bV[(nt * 8 + g) * PSTR + ca + 8];
                mma16816(oc[nt], pa[ks][0], pa[ks][1], pa[ks][2], pa[ks][3], B0, B1);
            }
        }
        d ^= 1;
    }

    // store unnormalized partials
    size_t rowg0 = (size_t)b * T_SEQ + iq * 64 + row0i;
    size_t rowg1 = rowg0 + 8;
    float* po = g_po + (size_t)chunk * B_SZ * T_SEQ * HD;
    #pragma unroll
    for (int nt = 0; nt < 8; nt++) {
        int cl = nt * 8 + t * 2;
        *(float2*)&po[rowg0 * HD + cl] = make_float2(oc[nt][0], oc[nt][1]);
        *(float2*)&po[rowg1 * HD + cl] = make_float2(oc[nt][2], oc[nt][3]);
    }
    if (t == 0) {
        g_pm[(size_t)chunk * B_SZ * T_SEQ + rowg0] = mr0;
        g_pm[(size_t)chunk * B_SZ * T_SEQ + rowg1] = mr1;
        g_pl[(size_t)chunk * B_SZ * T_SEQ + rowg0] = l0;
        g_pl[(size_t)chunk * B_SZ * T_SEQ + rowg1] = l1;
    }
}

// ---------------------------------------------------------------------------
// Kernel 3: combine split-KV partials. 16 threads per row (float4 per thread).
// ---------------------------------------------------------------------------
__global__ __launch_bounds__(256) void combine_kernel(float* __restrict__ out)
{
    const int idx = blockIdx.x * 256 + threadIdx.x;   // 16384*16 total
    const int row = idx >> 4;
    const int c4 = (idx & 15) * 4;
    const size_t NR = (size_t)B_SZ * T_SEQ;

    float m0 = g_pm[row];
    float m1 = g_pm[NR + row];
    float l0 = g_pl[row];
    float l1 = g_pl[NR + row];

    float mn = fmaxf(m0, m1);
    float a0 = ex2(m0 - mn);
    float a1 = ex2(m1 - mn);
    float inv = 1.f / (l0 * a0 + l1 * a1);

    float4 o0 = *(const float4*)&g_po[(size_t)row * HD + c4];
    float4 o1 = *(const float4*)&g_po[NR * HD + (size_t)row * HD + c4];
    float4 r;
    r.x = (o0.x * a0 + o1.x * a1) * inv;
    r.y = (o0.y * a0 + o1.y * a1) * inv;
    r.z = (o0.z * a0 + o1.z * a1) * inv;
    r.w = (o0.w * a0 + o1.w * a1) * inv;
    *(float4*)&out[(size_t)row * HD + c4] = r;
}

extern "C" void kernel_launch(void* const* d_in, const int* in_sizes, int n_in,
                              void* d_out, int out_size)
{
    const float* x  = (const float*)d_in[0];
    const float* Wq = (const float*)d_in[1];
    const float* Wk = (const float*)d_in[2];
    const float* Wv = (const float*)d_in[3];
    float* out = (float*)d_out;

    wt_kernel<<<dim3(C_DIM / 64, 3), 256>>>(Wq, Wk, Wv);
    proj2<<<(B_SZ * T_SEQ) / 128, 768>>>(x);
    flash5<<<dim3(T_SEQ / 64, NCHUNK, B_SZ), 128>>>();
    combine_kernel<<<(B_SZ * T_SEQ * 16) / 256, 256>>>(out);
}